// round 15
// baseline (speedup 1.0000x reference)
#include <cuda_runtime.h>
#include <cuda_bf16.h>
#include <cuda_fp16.h>
#include <math.h>
#include <stdint.h>

#define BN_EPS 1e-5f
#define SLOPE 0.1f

// -------- scratch (device globals; no allocation allowed) --------
__device__ float g_ms[1024 * 3328];        // pooled features
__device__ float g_fc1[1024 * 512];        // fc1 output
// fp16 fragment-major weights: [kg16][cog16][lane][8 halves]
__device__ __half g_w2h[12 * 8 * 32 * 8];   // conv2: K=192 -> 12 kg, 128 co -> 8 cog
__device__ __half g_w3h[24 * 16 * 32 * 8];  // conv3: K=384 -> 24 kg, 256 co -> 16 cog

// ---- helpers ----
__device__ __forceinline__ float tf32r(float x) {
    uint32_t u;
    asm("cvt.rna.tf32.f32 %0, %1;" : "=r"(u) : "f"(x));
    return __uint_as_float(u);
}
__device__ __forceinline__ uint32_t fbits(float x) { return __float_as_uint(x); }

__device__ __forceinline__ void mma8(float* d, const uint32_t* a, uint32_t b0, uint32_t b1) {
    asm volatile(
        "mma.sync.aligned.m16n8k8.row.col.f32.tf32.tf32.f32 "
        "{%0,%1,%2,%3}, {%4,%5,%6,%7}, {%8,%9}, {%0,%1,%2,%3};"
        : "+f"(d[0]), "+f"(d[1]), "+f"(d[2]), "+f"(d[3])
        : "r"(a[0]), "r"(a[1]), "r"(a[2]), "r"(a[3]), "r"(b0), "r"(b1));
}
__device__ __forceinline__ void mma16(float* d, const uint32_t* a, uint32_t b0, uint32_t b1) {
    asm volatile(
        "mma.sync.aligned.m16n8k16.row.col.f32.f16.f16.f32 "
        "{%0,%1,%2,%3}, {%4,%5,%6,%7}, {%8,%9}, {%0,%1,%2,%3};"
        : "+f"(d[0]), "+f"(d[1]), "+f"(d[2]), "+f"(d[3])
        : "r"(a[0]), "r"(a[1]), "r"(a[2]), "r"(a[3]), "r"(b0), "r"(b1));
}
__device__ __forceinline__ float lrelu(float v) { return v > 0.f ? v : SLOPE * v; }

// ============================================================================
// Prep: fold BN scale into w2/w3, fp16-round, pack per-lane m16n8k16 A
// fragments (same as R12, known-good).
// ============================================================================
__global__ __launch_bounds__(256) void prep_weights_kernel(
    const float* __restrict__ w2, const float* __restrict__ g2, const float* __restrict__ v2,
    const float* __restrict__ w3, const float* __restrict__ g3, const float* __restrict__ v3)
{
    int i = blockIdx.x * 256 + threadIdx.x;   // up to 98304
    if (i < 24576) {      // conv2: 12 kg x 8 cog x 32 lane x 8
        int f = i & 7, lane = (i >> 3) & 31, cog = (i >> 8) & 7, kg = i >> 11;
        int gid = lane >> 2, tig = lane & 3;
        int p = f >> 1, lo = f & 1;
        int k  = kg * 16 + 2 * tig + lo + ((p & 2) ? 8 : 0);
        int co = cog * 16 + gid + ((p & 1) ? 8 : 0);
        int tap = k >> 6, ci = k & 63;
        float a = g2[co] * rsqrtf(v2[co] + BN_EPS);
        g_w2h[i] = __float2half(a * w2[co * 192 + ci * 3 + tap]);
    }
    if (i < 98304) {      // conv3: 24 kg x 16 cog x 32 lane x 8
        int f = i & 7, lane = (i >> 3) & 31, cog = (i >> 8) & 15, kg = i >> 12;
        int gid = lane >> 2, tig = lane & 3;
        int p = f >> 1, lo = f & 1;
        int k  = kg * 16 + 2 * tig + lo + ((p & 2) ? 8 : 0);
        int co = cog * 16 + gid + ((p & 1) ? 8 : 0);
        int tap = k >> 7, ci = k & 127;
        float a = g3[co] * rsqrtf(v3[co] + BN_EPS);
        g_w3h[i] = __float2half(a * w3[co * 384 + ci * 3 + tap]);
    }
}

// ============================================================================
// FUSED kernel, t-split: grid (2, 1024).  blockIdx.x = th (t-half), .y = n.
// 256 threads, 8 warps as 4(M) x 2(N).  __launch_bounds__(256,2) -> 2 blk/SM.
//   conv1: fp32, t_local in [-2, 66) for this half (halo recompute).
//   conv2: M=128co x N=80t (66 valid) x K=192.  warp 32co x 40t.  d2[2][5][4].
//   conv3: M=256co x N=64t x K=384.            warp 64co x 32t.  d3[4][4][4].
// h1T[82][72] and h2T[66][136] fp16 transposed ([t_local][ci]) in dyn smem.
// Pools: each block writes only its 4 disjoint 16-t local bins per channel;
// finish_pool derives mid/global bins exactly.
// NOTE: static smem (~25.9KB) + dynamic (29.8KB) > 48KB -> NEEDS the
// cudaFuncSetAttribute opt-in (this was the R14 capture failure).
// ============================================================================
extern __shared__ __align__(16) unsigned char dsraw[];

__global__ __launch_bounds__(256, 2) void fused_conv_kernel(
    const float* __restrict__ x,
    const float* __restrict__ w1, const float* __restrict__ b1,
    const float* __restrict__ g1, const float* __restrict__ be1,
    const float* __restrict__ m1, const float* __restrict__ v1,
    const float* __restrict__ b2,
    const float* __restrict__ g2, const float* __restrict__ be2,
    const float* __restrict__ m2, const float* __restrict__ v2,
    const float* __restrict__ b3,
    const float* __restrict__ g3, const float* __restrict__ be3,
    const float* __restrict__ m3, const float* __restrict__ v3)
{
    __half* h1T = (__half*)dsraw;            // [82][72]  (row = t_local + 2)
    __half* h2T = h1T + 82 * 72;             // [66][136] (row = t' - (th*64-1))
    __shared__ float  xs[6 * 130];
    __shared__ float  w1f[64 * 18];
    __shared__ float  sh1[64], sh2[128], sh3[256];
    __shared__ __half wsh[2][4096];

    const int th  = blockIdx.x;              // 0 or 1: t-half
    const int n   = blockIdx.y;
    const int tid = threadIdx.x;

    // ---- zero h1T / h2T (halo correctness depends on this) ----
    {
        uint32_t* z1 = (uint32_t*)h1T;   // 2952 words
        uint32_t* z2 = (uint32_t*)h2T;   // 4488 words
        for (int i = tid; i < 2952; i += 256) z1[i] = 0u;
        for (int i = tid; i < 4488; i += 256) z2[i] = 0u;
    }

    // ---- scales / conv1 weights / input tile ----
    if (tid < 64) {
        float a1 = g1[tid] * rsqrtf(v1[tid] + BN_EPS);
        sh1[tid] = a1 * (b1[tid] - m1[tid]) + be1[tid];
    }
    if (tid < 128) {
        float a2 = g2[tid] * rsqrtf(v2[tid] + BN_EPS);
        sh2[tid] = a2 * (b2[tid] - m2[tid]) + be2[tid];
    }
    {
        float a3 = g3[tid] * rsqrtf(v3[tid] + BN_EPS);
        sh3[tid] = a3 * (b3[tid] - m3[tid]) + be3[tid];
    }
    for (int i = tid; i < 64 * 18; i += 256) {
        int co = i / 18;
        float a = g1[co] * rsqrtf(v1[co] + BN_EPS);
        w1f[i] = a * w1[i];
    }
    for (int i = tid; i < 768; i += 256) {
        int t = i / 6, c = i - t * 6;
        xs[c * 130 + 1 + t] = x[n * 768 + i];
    }
    if (tid < 6) { xs[tid * 130] = 0.f; xs[tid * 130 + 129] = 0.f; }
    __syncthreads();

    // ---- conv1 + BN + lrelu -> h1T rows 0..67 (valid global t only) ----
    for (int i = tid; i < 68 * 64; i += 256) {
        int row = i >> 6, co = i & 63;
        int t = th * 64 + row - 2;
        if (t >= 0 && t < 128) {
            float v = sh1[co];
            #pragma unroll
            for (int ci = 0; ci < 6; ++ci)
                #pragma unroll
                for (int k = 0; k < 3; ++k)
                    v += w1f[co * 18 + ci * 3 + k] * xs[ci * 130 + t + k];
            h1T[row * 72 + co] = __float2half(lrelu(v));
        }
    }

    const int lane = tid & 31, warp = tid >> 5;
    const int wm = warp >> 1;            // 0..3
    const int wn = warp & 1;             // 0..1
    const int gid = lane >> 2, tig = lane & 3;

    // ================== conv2: warp tile 32co x 40t, 12 k16 steps ==========
    {
        float d2[2][5][4];
        #pragma unroll
        for (int mt = 0; mt < 2; ++mt)
            #pragma unroll
            for (int nt = 0; nt < 5; ++nt)
                #pragma unroll
                for (int q = 0; q < 4; ++q) d2[mt][nt][q] = 0.f;

        // chunk = 1 kg = 2048 halves; one uint4 per thread
        uint4 pv = *(const uint4*)&g_w2h[tid * 8];
        *(uint4*)&wsh[0][tid * 8] = pv;
        __syncthreads();

        for (int kg = 0; kg < 12; ++kg) {
            int p = kg & 1;
            if (kg < 11)
                pv = *(const uint4*)&g_w2h[(kg + 1) * 2048 + tid * 8];
            int tap = (kg * 16) >> 6, cib = (kg * 16) & 63;
            uint32_t a[2][4];
            #pragma unroll
            for (int mt = 0; mt < 2; ++mt) {
                uint4 av = *(const uint4*)&wsh[p][(2 * wm + mt) * 256 + lane * 8];
                a[mt][0] = av.x; a[mt][1] = av.y; a[mt][2] = av.z; a[mt][3] = av.w;
            }
            #pragma unroll
            for (int nt = 0; nt < 5; ++nt) {
                int tt = wn * 40 + nt * 8 + gid;            // output col 0..79
                const __half* hb = h1T + (tt + tap) * 72 + cib + 2 * tig;
                uint32_t b0 = *(const uint32_t*)hb;
                uint32_t b1 = *(const uint32_t*)(hb + 8);
                mma16(d2[0][nt], a[0], b0, b1);
                mma16(d2[1][nt], a[1], b0, b1);
            }
            if (kg < 11)
                *(uint4*)&wsh[p ^ 1][tid * 8] = pv;
            __syncthreads();
        }

        // epilogue: valid outputs tt<66 AND global t' in [0,128) -> h2T
        #pragma unroll
        for (int mt = 0; mt < 2; ++mt) {
            int r0 = wm * 32 + mt * 16 + gid;
            int r1 = r0 + 8;
            float s0 = sh2[r0], s1 = sh2[r1];
            #pragma unroll
            for (int nt = 0; nt < 5; ++nt) {
                int tt = wn * 40 + nt * 8 + tig * 2;
                #pragma unroll
                for (int e = 0; e < 2; ++e) {
                    int tte = tt + e;
                    int tp = th * 64 - 1 + tte;              // global t'
                    if (tte < 66 && tp >= 0 && tp < 128) {
                        h2T[tte * 136 + r0] = __float2half(lrelu(d2[mt][nt][0 + e] + s0));
                        h2T[tte * 136 + r1] = __float2half(lrelu(d2[mt][nt][2 + e] + s1));
                    }
                }
            }
        }
    }

    // ================== conv3: warp tile 64co x 32t, 24 k16 steps ==========
    float d3[4][4][4];
    #pragma unroll
    for (int mt = 0; mt < 4; ++mt)
        #pragma unroll
        for (int nt = 0; nt < 4; ++nt)
            #pragma unroll
            for (int q = 0; q < 4; ++q) d3[mt][nt][q] = 0.f;

    {
        // chunk = 1 kg = 4096 halves; two uint4 per thread
        uint4 pv0 = *(const uint4*)&g_w3h[tid * 8];
        uint4 pv1 = *(const uint4*)&g_w3h[2048 + tid * 8];
        *(uint4*)&wsh[0][tid * 8]        = pv0;
        *(uint4*)&wsh[0][2048 + tid * 8] = pv1;
        __syncthreads();   // covers h2T epilogue writes + wsh[0] staging

        for (int kg = 0; kg < 24; ++kg) {
            int p = kg & 1;
            if (kg < 23) {
                pv0 = *(const uint4*)&g_w3h[(kg + 1) * 4096 + tid * 8];
                pv1 = *(const uint4*)&g_w3h[(kg + 1) * 4096 + 2048 + tid * 8];
            }
            int tap = (kg * 16) >> 7, cib = (kg * 16) & 127;
            uint32_t a[4][4];
            #pragma unroll
            for (int mt = 0; mt < 4; ++mt) {
                uint4 av = *(const uint4*)&wsh[p][(4 * wm + mt) * 256 + lane * 8];
                a[mt][0] = av.x; a[mt][1] = av.y; a[mt][2] = av.z; a[mt][3] = av.w;
            }
            #pragma unroll
            for (int nt = 0; nt < 4; ++nt) {
                int tt3 = wn * 32 + nt * 8 + gid;           // 0..63
                const __half* hb = h2T + (tt3 + tap) * 136 + cib + 2 * tig;
                uint32_t b0 = *(const uint32_t*)hb;
                uint32_t b1 = *(const uint32_t*)(hb + 8);
                #pragma unroll
                for (int mt = 0; mt < 4; ++mt)
                    mma16(d3[mt][nt], a[mt], b0, b1);
            }
            if (kg < 23) {
                *(uint4*)&wsh[p ^ 1][tid * 8]        = pv0;
                *(uint4*)&wsh[p ^ 1][2048 + tid * 8] = pv1;
            }
            __syncthreads();
        }
    }

    // ---- epilogue: shift + lrelu + LOCAL pools only ----
    // warp covers t in [wn*32, wn*32+32) of this half: bins th*4 + wn*2 + u.
    float* msn = g_ms + (long)n * 3328;
    #pragma unroll
    for (int mt = 0; mt < 4; ++mt) {
        int cl0 = wm * 64 + mt * 16 + gid;   // co 0..255
        int cl1 = cl0 + 8;
        float s0 = sh3[cl0], s1 = sh3[cl1];
        float p0[2] = {0.f, 0.f};
        float p1[2] = {0.f, 0.f};
        #pragma unroll
        for (int nt = 0; nt < 4; ++nt) {
            int u = nt >> 1;
            p0[u] += lrelu(d3[mt][nt][0] + s0) + lrelu(d3[mt][nt][1] + s0);
            p1[u] += lrelu(d3[mt][nt][2] + s1) + lrelu(d3[mt][nt][3] + s1);
        }
        #pragma unroll
        for (int u = 0; u < 2; ++u) {
            p0[u] += __shfl_xor_sync(0xffffffffu, p0[u], 1);
            p0[u] += __shfl_xor_sync(0xffffffffu, p0[u], 2);
            p1[u] += __shfl_xor_sync(0xffffffffu, p1[u], 1);
            p1[u] += __shfl_xor_sync(0xffffffffu, p1[u], 2);
        }
        if (tig == 0) {
            #pragma unroll
            for (int u = 0; u < 2; ++u) {
                msn[cl0 * 8 + th * 4 + wn * 2 + u] = p0[u] * (1.f / 16.f);
                msn[cl1 * 8 + th * 4 + wn * 2 + u] = p1[u] * (1.f / 16.f);
            }
        }
    }
}

// ============================================================================
// finish_pool: derive mid (32-t) and global (128-t) bins exactly from the 8
// local (16-t) bins.  grid 1024, 256 threads (one per channel).
// ============================================================================
__global__ __launch_bounds__(256) void finish_pool_kernel()
{
    int n = blockIdx.x, co = threadIdx.x;
    float* msn = g_ms + (long)n * 3328;
    float l[8];
    #pragma unroll
    for (int u = 0; u < 8; ++u) l[u] = msn[co * 8 + u];
    #pragma unroll
    for (int u = 0; u < 4; ++u)
        msn[2048 + co * 4 + u] = (l[2 * u] + l[2 * u + 1]) * 0.5f;
    msn[3072 + co] = (l[0] + l[1] + l[2] + l[3] + l[4] + l[5] + l[6] + l[7]) * 0.125f;
}

// ============================================================================
// FC kernel (tf32 mma, double-buffered smem, register prefetch) — unchanged.
// ============================================================================
template <int K, int Nc, bool RELU>
__global__ __launch_bounds__(256) void fc_mma_kernel(
    const float* __restrict__ A, const float* __restrict__ B,
    const float* __restrict__ bias, float* __restrict__ C)
{
    __shared__ float As[2][16 * 72];
    __shared__ float Bs[2][16 * 72];

    const int tid = threadIdx.x;
    const int m0 = blockIdx.y * 64, n0 = blockIdx.x * 64;
    const int lane = tid & 31, warp = tid >> 5;
    const int wm = warp >> 2, wn = warp & 3;
    const int gid = lane >> 2, tig = lane & 3;
    const int row = tid >> 2, q = tid & 3;

    const float* Ap = &A[(long)(m0 + row) * K + q * 4];
    const float* Bp = &B[(long)(n0 + row) * K + q * 4];

    float d[2][2][4];
    #pragma unroll
    for (int mt = 0; mt < 2; ++mt)
        #pragma unroll
        for (int nt = 0; nt < 2; ++nt)
            #pragma unroll
            for (int qq = 0; qq < 4; ++qq) d[mt][nt][qq] = 0.f;

    float4 av = *(const float4*)Ap;
    float4 bv = *(const float4*)Bp;
    {
        As[0][(q * 4 + 0) * 72 + row] = tf32r(av.x);
        As[0][(q * 4 + 1) * 72 + row] = tf32r(av.y);
        As[0][(q * 4 + 2) * 72 + row] = tf32r(av.z);
        As[0][(q * 4 + 3) * 72 + row] = tf32r(av.w);
        Bs[0][(q * 4 + 0) * 72 + row] = tf32r(bv.x);
        Bs[0][(q * 4 + 1) * 72 + row] = tf32r(bv.y);
        Bs[0][(q * 4 + 2) * 72 + row] = tf32r(bv.z);
        Bs[0][(q * 4 + 3) * 72 + row] = tf32r(bv.w);
    }
    __syncthreads();

    const int NC = K / 16;
    for (int kc = 0; kc < NC; ++kc) {
        int p = kc & 1;
        if (kc + 1 < NC) {
            av = *(const float4*)(Ap + (kc + 1) * 16);
            bv = *(const float4*)(Bp + (kc + 1) * 16);
        }
        #pragma unroll
        for (int ks = 0; ks < 2; ++ks) {
            const float* ar0 = &As[p][(ks * 8 + tig) * 72];
            const float* ar4 = &As[p][(ks * 8 + tig + 4) * 72];
            const float* br0 = &Bs[p][(ks * 8 + tig) * 72];
            const float* br4 = &Bs[p][(ks * 8 + tig + 4) * 72];
            uint32_t a[2][4];
            #pragma unroll
            for (int mt = 0; mt < 2; ++mt) {
                int m = wm * 32 + mt * 16 + gid;
                a[mt][0] = fbits(ar0[m]);  a[mt][1] = fbits(ar0[m + 8]);
                a[mt][2] = fbits(ar4[m]);  a[mt][3] = fbits(ar4[m + 8]);
            }
            #pragma unroll
            for (int nt = 0; nt < 2; ++nt) {
                int nn = wn * 16 + nt * 8 + gid;
                uint32_t b0 = fbits(br0[nn]);
                uint32_t b1 = fbits(br4[nn]);
                mma8(d[0][nt], a[0], b0, b1);
                mma8(d[1][nt], a[1], b0, b1);
            }
        }
        if (kc + 1 < NC) {
            int pn = p ^ 1;
            As[pn][(q * 4 + 0) * 72 + row] = tf32r(av.x);
            As[pn][(q * 4 + 1) * 72 + row] = tf32r(av.y);
            As[pn][(q * 4 + 2) * 72 + row] = tf32r(av.z);
            As[pn][(q * 4 + 3) * 72 + row] = tf32r(av.w);
            Bs[pn][(q * 4 + 0) * 72 + row] = tf32r(bv.x);
            Bs[pn][(q * 4 + 1) * 72 + row] = tf32r(bv.y);
            Bs[pn][(q * 4 + 2) * 72 + row] = tf32r(bv.z);
            Bs[pn][(q * 4 + 3) * 72 + row] = tf32r(bv.w);
        }
        __syncthreads();
    }

    #pragma unroll
    for (int mt = 0; mt < 2; ++mt) {
        int r0 = m0 + wm * 32 + mt * 16 + gid;
        int r1 = r0 + 8;
        #pragma unroll
        for (int nt = 0; nt < 2; ++nt) {
            int nn = n0 + wn * 16 + nt * 8 + tig * 2;
            float bb0 = bias[nn], bb1 = bias[nn + 1];
            float o0 = d[mt][nt][0] + bb0, o1 = d[mt][nt][1] + bb1;
            float o2 = d[mt][nt][2] + bb0, o3 = d[mt][nt][3] + bb1;
            if (RELU) {
                o0 = fmaxf(o0, 0.f); o1 = fmaxf(o1, 0.f);
                o2 = fmaxf(o2, 0.f); o3 = fmaxf(o3, 0.f);
            }
            float2 v0 = { o0, o1 }, v1 = { o2, o3 };
            *(float2*)&C[(long)r0 * Nc + nn] = v0;
            *(float2*)&C[(long)r1 * Nc + nn] = v1;
        }
    }
}

// ============================================================================
// metadata.txt / setup_inputs() dict order:
//   0:x 1:w1 2:b1 3:w2 4:b2 5:w3 6:b3
//   7:g1 8:be1 9:m1 10:v1  11:g2 12:be2 13:m2 14:v2  15:g3 16:be3 17:m3 18:v3
//   19:lw1 20:lb1 21:lw2 22:lb2
// ============================================================================
extern "C" void kernel_launch(void* const* d_in, const int* in_sizes, int n_in,
                              void* d_out, int out_size)
{
    const float* x   = (const float*)d_in[0];
    const float* w1  = (const float*)d_in[1];
    const float* b1  = (const float*)d_in[2];
    const float* w2  = (const float*)d_in[3];
    const float* b2  = (const float*)d_in[4];
    const float* w3  = (const float*)d_in[5];
    const float* b3  = (const float*)d_in[6];
    const float* g1  = (const float*)d_in[7];
    const float* be1 = (const float*)d_in[8];
    const float* m1  = (const float*)d_in[9];
    const float* v1  = (const float*)d_in[10];
    const float* g2  = (const float*)d_in[11];
    const float* be2 = (const float*)d_in[12];
    const float* m2  = (const float*)d_in[13];
    const float* v2  = (const float*)d_in[14];
    const float* g3  = (const float*)d_in[15];
    const float* be3 = (const float*)d_in[16];
    const float* m3  = (const float*)d_in[17];
    const float* v3  = (const float*)d_in[18];
    const float* lw1 = (const float*)d_in[19];
    const float* lb1 = (const float*)d_in[20];
    const float* lw2 = (const float*)d_in[21];
    const float* lb2 = (const float*)d_in[22];
    float* out = (float*)d_out;

    // dynamic smem: h1T 82*72 + h2T 66*136 halves = 29760 bytes.
    // static+dynamic > 48KB -> opt-in REQUIRED.
    const int fused_dyn = (82 * 72 + 66 * 136) * sizeof(__half);
    cudaFuncSetAttribute(fused_conv_kernel,
                         cudaFuncAttributeMaxDynamicSharedMemorySize, fused_dyn);

    prep_weights_kernel<<<384, 256>>>(w2, g2, v2, w3, g3, v3);

    fused_conv_kernel<<<dim3(2, 1024), 256, fused_dyn>>>(
        x, w1, b1, g1, be1, m1, v1,
        b2, g2, be2, m2, v2,
        b3, g3, be3, m3, v3);

    finish_pool_kernel<<<1024, 256>>>();

    float* fc1o;
    float* msp;
    cudaGetSymbolAddress((void**)&msp,  g_ms);
    cudaGetSymbolAddress((void**)&fc1o, g_fc1);

    fc_mma_kernel<3328, 512, true><<<dim3(8, 16), 256>>>(msp, lw1, lb1, fc1o);
    fc_mma_kernel<512, 256, false><<<dim3(4, 16), 256>>>(fc1o, lw2, lb2, out);
}

// round 16
// speedup vs baseline: 1.1710x; 1.1710x over previous
#include <cuda_runtime.h>
#include <cuda_bf16.h>
#include <cuda_fp16.h>
#include <math.h>
#include <stdint.h>

#define BN_EPS 1e-5f
#define SLOPE 0.1f

// -------- scratch (device globals; no allocation allowed) --------
__device__ float  g_ms[1024 * 3328];        // pooled features (fp32 local bins)
__device__ __half g_msh[1024 * 3328];       // fp16 feature vector for fc1
__device__ float  g_fc1[1024 * 512];        // fc1 output (fp32)
__device__ __half g_lw1h[512 * 3328];       // lw1 in fp16
// fp16 fragment-major weights: [kg16][cog16][lane][8 halves]
__device__ __half g_w2h[12 * 8 * 32 * 8];   // conv2: K=192 -> 12 kg, 128 co -> 8 cog
__device__ __half g_w3h[24 * 16 * 32 * 8];  // conv3: K=384 -> 24 kg, 256 co -> 16 cog

// ---- helpers ----
__device__ __forceinline__ float tf32r(float x) {
    uint32_t u;
    asm("cvt.rna.tf32.f32 %0, %1;" : "=r"(u) : "f"(x));
    return __uint_as_float(u);
}
__device__ __forceinline__ uint32_t fbits(float x) { return __float_as_uint(x); }

__device__ __forceinline__ void mma8(float* d, const uint32_t* a, uint32_t b0, uint32_t b1) {
    asm volatile(
        "mma.sync.aligned.m16n8k8.row.col.f32.tf32.tf32.f32 "
        "{%0,%1,%2,%3}, {%4,%5,%6,%7}, {%8,%9}, {%0,%1,%2,%3};"
        : "+f"(d[0]), "+f"(d[1]), "+f"(d[2]), "+f"(d[3])
        : "r"(a[0]), "r"(a[1]), "r"(a[2]), "r"(a[3]), "r"(b0), "r"(b1));
}
__device__ __forceinline__ void mma16(float* d, const uint32_t* a, uint32_t b0, uint32_t b1) {
    asm volatile(
        "mma.sync.aligned.m16n8k16.row.col.f32.f16.f16.f32 "
        "{%0,%1,%2,%3}, {%4,%5,%6,%7}, {%8,%9}, {%0,%1,%2,%3};"
        : "+f"(d[0]), "+f"(d[1]), "+f"(d[2]), "+f"(d[3])
        : "r"(a[0]), "r"(a[1]), "r"(a[2]), "r"(a[3]), "r"(b0), "r"(b1));
}
__device__ __forceinline__ float lrelu(float v) { return v > 0.f ? v : SLOPE * v; }

// ============================================================================
// Prep: fold BN scale into w2/w3, fp16-round, pack per-lane m16n8k16 A frags.
// ============================================================================
__global__ __launch_bounds__(256) void prep_weights_kernel(
    const float* __restrict__ w2, const float* __restrict__ g2, const float* __restrict__ v2,
    const float* __restrict__ w3, const float* __restrict__ g3, const float* __restrict__ v3)
{
    int i = blockIdx.x * 256 + threadIdx.x;   // up to 98304
    if (i < 24576) {
        int f = i & 7, lane = (i >> 3) & 31, cog = (i >> 8) & 7, kg = i >> 11;
        int gid = lane >> 2, tig = lane & 3;
        int p = f >> 1, lo = f & 1;
        int k  = kg * 16 + 2 * tig + lo + ((p & 2) ? 8 : 0);
        int co = cog * 16 + gid + ((p & 1) ? 8 : 0);
        int tap = k >> 6, ci = k & 63;
        float a = g2[co] * rsqrtf(v2[co] + BN_EPS);
        g_w2h[i] = __float2half(a * w2[co * 192 + ci * 3 + tap]);
    }
    if (i < 98304) {
        int f = i & 7, lane = (i >> 3) & 31, cog = (i >> 8) & 15, kg = i >> 12;
        int gid = lane >> 2, tig = lane & 3;
        int p = f >> 1, lo = f & 1;
        int k  = kg * 16 + 2 * tig + lo + ((p & 2) ? 8 : 0);
        int co = cog * 16 + gid + ((p & 1) ? 8 : 0);
        int tap = k >> 7, ci = k & 127;
        float a = g3[co] * rsqrtf(v3[co] + BN_EPS);
        g_w3h[i] = __float2half(a * w3[co * 384 + ci * 3 + tap]);
    }
}

// fc1 weight fp16 conversion
__global__ __launch_bounds__(256) void prep_fc1_kernel(const float* __restrict__ lw1)
{
    int i = blockIdx.x * 256 + threadIdx.x;
    if (i < 512 * 3328) g_lw1h[i] = __float2half(lw1[i]);
}

// ============================================================================
// FUSED kernel, t-split (identical to R15 pass): grid (2,1024), 256 thr,
// __launch_bounds__(256,2).  See R15 comments.
// ============================================================================
extern __shared__ __align__(16) unsigned char dsraw[];

__global__ __launch_bounds__(256, 2) void fused_conv_kernel(
    const float* __restrict__ x,
    const float* __restrict__ w1, const float* __restrict__ b1,
    const float* __restrict__ g1, const float* __restrict__ be1,
    const float* __restrict__ m1, const float* __restrict__ v1,
    const float* __restrict__ b2,
    const float* __restrict__ g2, const float* __restrict__ be2,
    const float* __restrict__ m2, const float* __restrict__ v2,
    const float* __restrict__ b3,
    const float* __restrict__ g3, const float* __restrict__ be3,
    const float* __restrict__ m3, const float* __restrict__ v3)
{
    __half* h1T = (__half*)dsraw;            // [82][72]
    __half* h2T = h1T + 82 * 72;             // [66][136]
    __shared__ float  xs[6 * 130];
    __shared__ float  w1f[64 * 18];
    __shared__ float  sh1[64], sh2[128], sh3[256];
    __shared__ __half wsh[2][4096];

    const int th  = blockIdx.x;
    const int n   = blockIdx.y;
    const int tid = threadIdx.x;

    {
        uint32_t* z1 = (uint32_t*)h1T;
        uint32_t* z2 = (uint32_t*)h2T;
        for (int i = tid; i < 2952; i += 256) z1[i] = 0u;
        for (int i = tid; i < 4488; i += 256) z2[i] = 0u;
    }

    if (tid < 64) {
        float a1 = g1[tid] * rsqrtf(v1[tid] + BN_EPS);
        sh1[tid] = a1 * (b1[tid] - m1[tid]) + be1[tid];
    }
    if (tid < 128) {
        float a2 = g2[tid] * rsqrtf(v2[tid] + BN_EPS);
        sh2[tid] = a2 * (b2[tid] - m2[tid]) + be2[tid];
    }
    {
        float a3 = g3[tid] * rsqrtf(v3[tid] + BN_EPS);
        sh3[tid] = a3 * (b3[tid] - m3[tid]) + be3[tid];
    }
    for (int i = tid; i < 64 * 18; i += 256) {
        int co = i / 18;
        float a = g1[co] * rsqrtf(v1[co] + BN_EPS);
        w1f[i] = a * w1[i];
    }
    for (int i = tid; i < 768; i += 256) {
        int t = i / 6, c = i - t * 6;
        xs[c * 130 + 1 + t] = x[n * 768 + i];
    }
    if (tid < 6) { xs[tid * 130] = 0.f; xs[tid * 130 + 129] = 0.f; }
    __syncthreads();

    for (int i = tid; i < 68 * 64; i += 256) {
        int row = i >> 6, co = i & 63;
        int t = th * 64 + row - 2;
        if (t >= 0 && t < 128) {
            float v = sh1[co];
            #pragma unroll
            for (int ci = 0; ci < 6; ++ci)
                #pragma unroll
                for (int k = 0; k < 3; ++k)
                    v += w1f[co * 18 + ci * 3 + k] * xs[ci * 130 + t + k];
            h1T[row * 72 + co] = __float2half(lrelu(v));
        }
    }

    const int lane = tid & 31, warp = tid >> 5;
    const int wm = warp >> 1;
    const int wn = warp & 1;
    const int gid = lane >> 2, tig = lane & 3;

    // conv2
    {
        float d2[2][5][4];
        #pragma unroll
        for (int mt = 0; mt < 2; ++mt)
            #pragma unroll
            for (int nt = 0; nt < 5; ++nt)
                #pragma unroll
                for (int q = 0; q < 4; ++q) d2[mt][nt][q] = 0.f;

        uint4 pv = *(const uint4*)&g_w2h[tid * 8];
        *(uint4*)&wsh[0][tid * 8] = pv;
        __syncthreads();

        for (int kg = 0; kg < 12; ++kg) {
            int p = kg & 1;
            if (kg < 11)
                pv = *(const uint4*)&g_w2h[(kg + 1) * 2048 + tid * 8];
            int tap = (kg * 16) >> 6, cib = (kg * 16) & 63;
            uint32_t a[2][4];
            #pragma unroll
            for (int mt = 0; mt < 2; ++mt) {
                uint4 av = *(const uint4*)&wsh[p][(2 * wm + mt) * 256 + lane * 8];
                a[mt][0] = av.x; a[mt][1] = av.y; a[mt][2] = av.z; a[mt][3] = av.w;
            }
            #pragma unroll
            for (int nt = 0; nt < 5; ++nt) {
                int tt = wn * 40 + nt * 8 + gid;
                const __half* hb = h1T + (tt + tap) * 72 + cib + 2 * tig;
                uint32_t b0 = *(const uint32_t*)hb;
                uint32_t b1 = *(const uint32_t*)(hb + 8);
                mma16(d2[0][nt], a[0], b0, b1);
                mma16(d2[1][nt], a[1], b0, b1);
            }
            if (kg < 11)
                *(uint4*)&wsh[p ^ 1][tid * 8] = pv;
            __syncthreads();
        }

        #pragma unroll
        for (int mt = 0; mt < 2; ++mt) {
            int r0 = wm * 32 + mt * 16 + gid;
            int r1 = r0 + 8;
            float s0 = sh2[r0], s1 = sh2[r1];
            #pragma unroll
            for (int nt = 0; nt < 5; ++nt) {
                int tt = wn * 40 + nt * 8 + tig * 2;
                #pragma unroll
                for (int e = 0; e < 2; ++e) {
                    int tte = tt + e;
                    int tp = th * 64 - 1 + tte;
                    if (tte < 66 && tp >= 0 && tp < 128) {
                        h2T[tte * 136 + r0] = __float2half(lrelu(d2[mt][nt][0 + e] + s0));
                        h2T[tte * 136 + r1] = __float2half(lrelu(d2[mt][nt][2 + e] + s1));
                    }
                }
            }
        }
    }

    // conv3
    float d3[4][4][4];
    #pragma unroll
    for (int mt = 0; mt < 4; ++mt)
        #pragma unroll
        for (int nt = 0; nt < 4; ++nt)
            #pragma unroll
            for (int q = 0; q < 4; ++q) d3[mt][nt][q] = 0.f;

    {
        uint4 pv0 = *(const uint4*)&g_w3h[tid * 8];
        uint4 pv1 = *(const uint4*)&g_w3h[2048 + tid * 8];
        *(uint4*)&wsh[0][tid * 8]        = pv0;
        *(uint4*)&wsh[0][2048 + tid * 8] = pv1;
        __syncthreads();

        for (int kg = 0; kg < 24; ++kg) {
            int p = kg & 1;
            if (kg < 23) {
                pv0 = *(const uint4*)&g_w3h[(kg + 1) * 4096 + tid * 8];
                pv1 = *(const uint4*)&g_w3h[(kg + 1) * 4096 + 2048 + tid * 8];
            }
            int tap = (kg * 16) >> 7, cib = (kg * 16) & 127;
            uint32_t a[4][4];
            #pragma unroll
            for (int mt = 0; mt < 4; ++mt) {
                uint4 av = *(const uint4*)&wsh[p][(4 * wm + mt) * 256 + lane * 8];
                a[mt][0] = av.x; a[mt][1] = av.y; a[mt][2] = av.z; a[mt][3] = av.w;
            }
            #pragma unroll
            for (int nt = 0; nt < 4; ++nt) {
                int tt3 = wn * 32 + nt * 8 + gid;
                const __half* hb = h2T + (tt3 + tap) * 136 + cib + 2 * tig;
                uint32_t b0 = *(const uint32_t*)hb;
                uint32_t b1 = *(const uint32_t*)(hb + 8);
                #pragma unroll
                for (int mt = 0; mt < 4; ++mt)
                    mma16(d3[mt][nt], a[mt], b0, b1);
            }
            if (kg < 23) {
                *(uint4*)&wsh[p ^ 1][tid * 8]        = pv0;
                *(uint4*)&wsh[p ^ 1][2048 + tid * 8] = pv1;
            }
            __syncthreads();
        }
    }

    // local pools
    float* msn = g_ms + (long)n * 3328;
    #pragma unroll
    for (int mt = 0; mt < 4; ++mt) {
        int cl0 = wm * 64 + mt * 16 + gid;
        int cl1 = cl0 + 8;
        float s0 = sh3[cl0], s1 = sh3[cl1];
        float p0[2] = {0.f, 0.f};
        float p1[2] = {0.f, 0.f};
        #pragma unroll
        for (int nt = 0; nt < 4; ++nt) {
            int u = nt >> 1;
            p0[u] += lrelu(d3[mt][nt][0] + s0) + lrelu(d3[mt][nt][1] + s0);
            p1[u] += lrelu(d3[mt][nt][2] + s1) + lrelu(d3[mt][nt][3] + s1);
        }
        #pragma unroll
        for (int u = 0; u < 2; ++u) {
            p0[u] += __shfl_xor_sync(0xffffffffu, p0[u], 1);
            p0[u] += __shfl_xor_sync(0xffffffffu, p0[u], 2);
            p1[u] += __shfl_xor_sync(0xffffffffu, p1[u], 1);
            p1[u] += __shfl_xor_sync(0xffffffffu, p1[u], 2);
        }
        if (tig == 0) {
            #pragma unroll
            for (int u = 0; u < 2; ++u) {
                msn[cl0 * 8 + th * 4 + wn * 2 + u] = p0[u] * (1.f / 16.f);
                msn[cl1 * 8 + th * 4 + wn * 2 + u] = p1[u] * (1.f / 16.f);
            }
        }
    }
}

// ============================================================================
// finish_pool: derive mid/global bins from locals; emit ENTIRE 3328-vector as
// fp16 into g_msh (fc1's A operand).  grid 1024, 256 threads.
// ============================================================================
__global__ __launch_bounds__(256) void finish_pool_kernel()
{
    int n = blockIdx.x, co = threadIdx.x;
    float*  msn  = g_ms  + (long)n * 3328;
    __half* msnh = g_msh + (long)n * 3328;
    float l[8];
    #pragma unroll
    for (int u = 0; u < 8; ++u) {
        l[u] = msn[co * 8 + u];
        msnh[co * 8 + u] = __float2half(l[u]);
    }
    #pragma unroll
    for (int u = 0; u < 4; ++u)
        msnh[2048 + co * 4 + u] = __float2half((l[2 * u] + l[2 * u + 1]) * 0.5f);
    msnh[3072 + co] = __float2half(
        (l[0] + l[1] + l[2] + l[3] + l[4] + l[5] + l[6] + l[7]) * 0.125f);
}

// ============================================================================
// fc1 (fp16 m16n8k16): C[1024][512] = relu(A[1024][3328] B[512][3328]^T + b)
// tile 32m x 64n, grid (8, 32) = 256 blocks, 256 threads (8 warps 2M x 4N,
// warp 16m x 16n).  K chunks of 32, double-buffered register prefetch.
// A/B staged [row][k] (stride 40 halves -> conflict-free 4B fragment loads).
// ============================================================================
__global__ __launch_bounds__(256) void fc1_f16_kernel(
    const __half* __restrict__ A, const __half* __restrict__ B,
    const float* __restrict__ bias, float* __restrict__ C)
{
    __shared__ __half As[2][32 * 40];
    __shared__ __half Bs[2][64 * 40];

    const int tid = threadIdx.x;
    const int m0 = blockIdx.y * 32, n0 = blockIdx.x * 64;
    const int lane = tid & 31, warp = tid >> 5;
    const int wm = warp >> 2, wn = warp & 3;       // wm 0..1, wn 0..3
    const int gid = lane >> 2, tig = lane & 3;
    const int row = tid >> 2, q = tid & 3;         // staging: 64 rows x 4 q
    const int K = 3328;

    const __half* Bp = B + (long)(n0 + row) * K + q * 8;
    const __half* Ap = A + (long)(m0 + row) * K + q * 8;   // valid for tid<128

    float d[2][4];
    #pragma unroll
    for (int nt = 0; nt < 2; ++nt)
        #pragma unroll
        for (int qq = 0; qq < 4; ++qq) d[nt][qq] = 0.f;

    uint4 pa, pb;
    pb = *(const uint4*)Bp;
    if (tid < 128) pa = *(const uint4*)Ap;
    *(uint4*)&Bs[0][row * 40 + q * 8] = pb;
    if (tid < 128) *(uint4*)&As[0][row * 40 + q * 8] = pa;
    __syncthreads();

    for (int kc = 0; kc < 104; ++kc) {
        int p = kc & 1;
        if (kc < 103) {
            pb = *(const uint4*)(Bp + (kc + 1) * 32);
            if (tid < 128) pa = *(const uint4*)(Ap + (kc + 1) * 32);
        }
        #pragma unroll
        for (int ks = 0; ks < 2; ++ks) {
            uint32_t a[4];
            a[0] = *(const uint32_t*)&As[p][(wm * 16 + gid)     * 40 + ks * 16 + 2 * tig];
            a[1] = *(const uint32_t*)&As[p][(wm * 16 + gid + 8) * 40 + ks * 16 + 2 * tig];
            a[2] = *(const uint32_t*)&As[p][(wm * 16 + gid)     * 40 + ks * 16 + 2 * tig + 8];
            a[3] = *(const uint32_t*)&As[p][(wm * 16 + gid + 8) * 40 + ks * 16 + 2 * tig + 8];
            #pragma unroll
            for (int nt = 0; nt < 2; ++nt) {
                int nn = wn * 16 + nt * 8 + gid;
                uint32_t b0 = *(const uint32_t*)&Bs[p][nn * 40 + ks * 16 + 2 * tig];
                uint32_t b1 = *(const uint32_t*)&Bs[p][nn * 40 + ks * 16 + 2 * tig + 8];
                mma16(d[nt], a, b0, b1);
            }
        }
        if (kc < 103) {
            int pn = p ^ 1;
            *(uint4*)&Bs[pn][row * 40 + q * 8] = pb;
            if (tid < 128) *(uint4*)&As[pn][row * 40 + q * 8] = pa;
        }
        __syncthreads();
    }

    // epilogue: bias + relu -> C fp32
    #pragma unroll
    for (int nt = 0; nt < 2; ++nt) {
        int nn = n0 + wn * 16 + nt * 8 + tig * 2;
        float b0f = bias[nn], b1f = bias[nn + 1];
        int r0 = m0 + wm * 16 + gid, r1 = r0 + 8;
        float2 v0 = { fmaxf(d[nt][0] + b0f, 0.f), fmaxf(d[nt][1] + b1f, 0.f) };
        float2 v1 = { fmaxf(d[nt][2] + b0f, 0.f), fmaxf(d[nt][3] + b1f, 0.f) };
        *(float2*)&C[(long)r0 * 512 + nn] = v0;
        *(float2*)&C[(long)r1 * 512 + nn] = v1;
    }
}

// ============================================================================
// fc2 (tf32 mma, unchanged): C[1024][256] = A[1024][512] lw2^T + lb2
// ============================================================================
template <int K, int Nc, bool RELU>
__global__ __launch_bounds__(256) void fc_mma_kernel(
    const float* __restrict__ A, const float* __restrict__ B,
    const float* __restrict__ bias, float* __restrict__ C)
{
    __shared__ float As[2][16 * 72];
    __shared__ float Bs[2][16 * 72];

    const int tid = threadIdx.x;
    const int m0 = blockIdx.y * 64, n0 = blockIdx.x * 64;
    const int lane = tid & 31, warp = tid >> 5;
    const int wm = warp >> 2, wn = warp & 3;
    const int gid = lane >> 2, tig = lane & 3;
    const int row = tid >> 2, q = tid & 3;

    const float* Ap = &A[(long)(m0 + row) * K + q * 4];
    const float* Bp = &B[(long)(n0 + row) * K + q * 4];

    float d[2][2][4];
    #pragma unroll
    for (int mt = 0; mt < 2; ++mt)
        #pragma unroll
        for (int nt = 0; nt < 2; ++nt)
            #pragma unroll
            for (int qq = 0; qq < 4; ++qq) d[mt][nt][qq] = 0.f;

    float4 av = *(const float4*)Ap;
    float4 bv = *(const float4*)Bp;
    {
        As[0][(q * 4 + 0) * 72 + row] = tf32r(av.x);
        As[0][(q * 4 + 1) * 72 + row] = tf32r(av.y);
        As[0][(q * 4 + 2) * 72 + row] = tf32r(av.z);
        As[0][(q * 4 + 3) * 72 + row] = tf32r(av.w);
        Bs[0][(q * 4 + 0) * 72 + row] = tf32r(bv.x);
        Bs[0][(q * 4 + 1) * 72 + row] = tf32r(bv.y);
        Bs[0][(q * 4 + 2) * 72 + row] = tf32r(bv.z);
        Bs[0][(q * 4 + 3) * 72 + row] = tf32r(bv.w);
    }
    __syncthreads();

    const int NC = K / 16;
    for (int kc = 0; kc < NC; ++kc) {
        int p = kc & 1;
        if (kc + 1 < NC) {
            av = *(const float4*)(Ap + (kc + 1) * 16);
            bv = *(const float4*)(Bp + (kc + 1) * 16);
        }
        #pragma unroll
        for (int ks = 0; ks < 2; ++ks) {
            const float* ar0 = &As[p][(ks * 8 + tig) * 72];
            const float* ar4 = &As[p][(ks * 8 + tig + 4) * 72];
            const float* br0 = &Bs[p][(ks * 8 + tig) * 72];
            const float* br4 = &Bs[p][(ks * 8 + tig + 4) * 72];
            uint32_t a[2][4];
            #pragma unroll
            for (int mt = 0; mt < 2; ++mt) {
                int m = wm * 32 + mt * 16 + gid;
                a[mt][0] = fbits(ar0[m]);  a[mt][1] = fbits(ar0[m + 8]);
                a[mt][2] = fbits(ar4[m]);  a[mt][3] = fbits(ar4[m + 8]);
            }
            #pragma unroll
            for (int nt = 0; nt < 2; ++nt) {
                int nn = wn * 16 + nt * 8 + gid;
                uint32_t b0 = fbits(br0[nn]);
                uint32_t b1 = fbits(br4[nn]);
                mma8(d[0][nt], a[0], b0, b1);
                mma8(d[1][nt], a[1], b0, b1);
            }
        }
        if (kc + 1 < NC) {
            int pn = p ^ 1;
            As[pn][(q * 4 + 0) * 72 + row] = tf32r(av.x);
            As[pn][(q * 4 + 1) * 72 + row] = tf32r(av.y);
            As[pn][(q * 4 + 2) * 72 + row] = tf32r(av.z);
            As[pn][(q * 4 + 3) * 72 + row] = tf32r(av.w);
            Bs[pn][(q * 4 + 0) * 72 + row] = tf32r(bv.x);
            Bs[pn][(q * 4 + 1) * 72 + row] = tf32r(bv.y);
            Bs[pn][(q * 4 + 2) * 72 + row] = tf32r(bv.z);
            Bs[pn][(q * 4 + 3) * 72 + row] = tf32r(bv.w);
        }
        __syncthreads();
    }

    #pragma unroll
    for (int mt = 0; mt < 2; ++mt) {
        int r0 = m0 + wm * 32 + mt * 16 + gid;
        int r1 = r0 + 8;
        #pragma unroll
        for (int nt = 0; nt < 2; ++nt) {
            int nn = n0 + wn * 16 + nt * 8 + tig * 2;
            float bb0 = bias[nn], bb1 = bias[nn + 1];
            float o0 = d[mt][nt][0] + bb0, o1 = d[mt][nt][1] + bb1;
            float o2 = d[mt][nt][2] + bb0, o3 = d[mt][nt][3] + bb1;
            if (RELU) {
                o0 = fmaxf(o0, 0.f); o1 = fmaxf(o1, 0.f);
                o2 = fmaxf(o2, 0.f); o3 = fmaxf(o3, 0.f);
            }
            float2 v0 = { o0, o1 }, v1 = { o2, o3 };
            *(float2*)&C[(long)r0 * Nc + nn] = v0;
            *(float2*)&C[(long)r1 * Nc + nn] = v1;
        }
    }
}

// ============================================================================
// metadata.txt / setup_inputs() dict order:
//   0:x 1:w1 2:b1 3:w2 4:b2 5:w3 6:b3
//   7:g1 8:be1 9:m1 10:v1  11:g2 12:be2 13:m2 14:v2  15:g3 16:be3 17:m3 18:v3
//   19:lw1 20:lb1 21:lw2 22:lb2
// ============================================================================
extern "C" void kernel_launch(void* const* d_in, const int* in_sizes, int n_in,
                              void* d_out, int out_size)
{
    const float* x   = (const float*)d_in[0];
    const float* w1  = (const float*)d_in[1];
    const float* b1  = (const float*)d_in[2];
    const float* w2  = (const float*)d_in[3];
    const float* b2  = (const float*)d_in[4];
    const float* w3  = (const float*)d_in[5];
    const float* b3  = (const float*)d_in[6];
    const float* g1  = (const float*)d_in[7];
    const float* be1 = (const float*)d_in[8];
    const float* m1  = (const float*)d_in[9];
    const float* v1  = (const float*)d_in[10];
    const float* g2  = (const float*)d_in[11];
    const float* be2 = (const float*)d_in[12];
    const float* m2  = (const float*)d_in[13];
    const float* v2  = (const float*)d_in[14];
    const float* g3  = (const float*)d_in[15];
    const float* be3 = (const float*)d_in[16];
    const float* m3  = (const float*)d_in[17];
    const float* v3  = (const float*)d_in[18];
    const float* lw1 = (const float*)d_in[19];
    const float* lb1 = (const float*)d_in[20];
    const float* lw2 = (const float*)d_in[21];
    const float* lb2 = (const float*)d_in[22];
    float* out = (float*)d_out;

    // fused: static+dynamic > 48KB -> opt-in REQUIRED
    const int fused_dyn = (82 * 72 + 66 * 136) * sizeof(__half);
    cudaFuncSetAttribute(fused_conv_kernel,
                         cudaFuncAttributeMaxDynamicSharedMemorySize, fused_dyn);

    prep_weights_kernel<<<384, 256>>>(w2, g2, v2, w3, g3, v3);
    prep_fc1_kernel<<<6656, 256>>>(lw1);

    fused_conv_kernel<<<dim3(2, 1024), 256, fused_dyn>>>(
        x, w1, b1, g1, be1, m1, v1,
        b2, g2, be2, m2, v2,
        b3, g3, be3, m3, v3);

    finish_pool_kernel<<<1024, 256>>>();

    float* fc1o;
    __half* msh;
    __half* lw1h;
    cudaGetSymbolAddress((void**)&msh,  g_msh);
    cudaGetSymbolAddress((void**)&lw1h, g_lw1h);
    cudaGetSymbolAddress((void**)&fc1o, g_fc1);

    fc1_f16_kernel<<<dim3(8, 32), 256>>>(msh, lw1h, lb1, fc1o);
    fc_mma_kernel<512, 256, false><<<dim3(4, 16), 256>>>(fc1o, lw2, lb2, out);
}